// round 15
// baseline (speedup 1.0000x reference)
#include <cuda_runtime.h>
#include <math.h>
#include <stdint.h>

// Problem constants (fixed by the reference's setup_inputs)
#define NROWS   8192           // B
#define SLEN    4096           // S
#define NSUPER  32             // 32 tiles of 128 steps per row
#define TILEB   2048           // 128 steps * 16 B
#define D       4              // ring depth (tiles in flight per warp)
#define BLOCK   128            // 4 warps/block, one row per warp

#define DELTA_T 900.0
// COOLING_SIGN = -1.0

__device__ __forceinline__ double bounded_d(double raw, double lo, double hi) {
    double s = 1.0 / (1.0 + exp(-raw));
    return lo + (hi - lo) * s;
}

__device__ __forceinline__ uint32_t smem_u32(const void* p) {
    uint32_t a;
    asm("{ .reg .u64 t; cvta.to.shared.u64 t, %1; cvt.u32.u64 %0, t; }"
        : "=r"(a) : "l"(p));
    return a;
}

__device__ __forceinline__ void mbar_init(uint32_t mbar, uint32_t count) {
    asm volatile("mbarrier.init.shared.b64 [%0], %1;" :: "r"(mbar), "r"(count) : "memory");
}
__device__ __forceinline__ void mbar_expect_tx(uint32_t mbar, uint32_t bytes) {
    asm volatile("mbarrier.arrive.expect_tx.shared.b64 _, [%0], %1;"
                 :: "r"(mbar), "r"(bytes) : "memory");
}
__device__ __forceinline__ void bulk_g2s(uint32_t dst, const void* src,
                                         uint32_t bytes, uint32_t mbar) {
    asm volatile("cp.async.bulk.shared::cta.global.mbarrier::complete_tx::bytes "
                 "[%0], [%1], %2, [%3];"
                 :: "r"(dst), "l"(src), "r"(bytes), "r"(mbar) : "memory");
}
__device__ __forceinline__ void mbar_wait(uint32_t mbar, uint32_t parity) {
    asm volatile(
        "{\n\t"
        ".reg .pred P;\n\t"
        "WAIT_%=:\n\t"
        "mbarrier.try_wait.parity.shared.b64 P, [%0], %1;\n\t"
        "@!P bra WAIT_%=;\n\t"
        "}"
        :: "r"(mbar), "r"(parity) : "memory");
}

// One warp per batch row; t' = a*t + b_s with constant a, resolved 32 steps
// per round via a warp prefix scan (R4 consumer — proven 1.85e-7).
//
// R13 post-mortem: DRAM clamps at ~59% (~4.7 TB/s) across PF depth, occupancy
// and shuffle-count variations => per-SM outstanding-miss cap on the LDG path
// (~19 KB in flight/SM by Little's law). This version moves the read stream
// onto the TMA bulk-async path: per-warp 4-deep ring of 2 KB smem tiles filled
// by cp.async.bulk + mbarrier, consumer reads tiles via conflict-free LDS.128
// (16 B lane stride). TMA tracking is engine-side, not MSHR-side.
__global__ __launch_bounds__(BLOCK)
void rc_scan_kernel(const float*  __restrict__ in,
                    const float*  __restrict__ pR,
                    const float*  __restrict__ pC,
                    const float*  __restrict__ pA,
                    const float*  __restrict__ pG,
                    float*        __restrict__ out)
{
    __shared__ __align__(128) unsigned char tiles[4][D][TILEB];  // 32 KB
    __shared__ __align__(8)   unsigned long long mbars[4][D];

    const int wib  = threadIdx.x >> 5;             // warp in block (0..3)
    const int lane = threadIdx.x & 31;
    const int grow = blockIdx.x * 4 + wib;         // row index

    // --- scalar parameters (sigmoid-bounded), computed in double, negligible ---
    const double R = bounded_d((double)*pR, 1e-4, 0.2);
    const double C = bounded_d((double)*pC, 1e5, 1e8);
    const double A = bounded_d((double)*pA, 0.0, 0.2);
    const double G = bounded_d((double)*pG, 1.0, 20000.0);

    const double dtC = DELTA_T / C;
    const double a_d = 1.0 - dtC / R;       // ~0.9633 for given inputs
    const float  a   = (float)a_d;
    const float  kTo = (float)(dtC / R);    // coeff of t_out
    const float  kU  = (float)(-G * dtC);   // COOLING_SIGN * g * dt/C
    const float  kSo = (float)(A * dtC);    // coeff of solar

    const double la   = log(a_d);
    const float  apow = (float)exp( la * (double)lane);   // a^lane
    const float  ainv = (float)exp(-la * (double)lane);   // a^-lane

    const char* rowg = (const char*)(in + (size_t)grow * SLEN * 4);
    float*      orow = out + (size_t)grow * SLEN;

    // warp-private barrier / tile smem addresses
    uint32_t mb[D], tl[D];
    #pragma unroll
    for (int s = 0; s < D; s++) {
        mb[s] = smem_u32(&mbars[wib][s]);
        tl[s] = smem_u32(&tiles[wib][s][0]);
    }

    if (lane == 0) {
        #pragma unroll
        for (int s = 0; s < D; s++) mbar_init(mb[s], 1);
    }
    __syncthreads();   // all barriers initialized before any TMA targets them

    // prologue: fill the ring (D independent 2 KB bulk loads in flight)
    if (lane == 0) {
        #pragma unroll
        for (int s = 0; s < D; s++) {
            mbar_expect_tx(mb[s], TILEB);
            bulk_g2s(tl[s], rowg + s * TILEB, TILEB, mb[s]);
        }
    }

    // initial carry = t_in[b, 0] (channel x of step 0)
    float t = __ldg((const float*)rowg);

    for (int r = 0; r < NSUPER; r++) {
        const int slot = r & (D - 1);
        const int ph   = (r >> 2) & 1;          // phase flips each ring wrap

        mbar_wait(mb[slot], ph);
        const float4* tp = (const float4*)&tiles[wib][slot][0];

        #pragma unroll
        for (int j = 0; j < 4; j++) {
            // conflict-free LDS.128: 16 B lane stride spans distinct banks
            const float4 v = tp[j * 32 + lane];

            // b_s = kTo*t_out + kU*u + kSo*solar ; rescale for the prefix
            float b = fmaf(kTo, v.y, fmaf(kU, v.z, kSo * v.w));
            float c = b * ainv;

            // inclusive warp prefix sum of c
            #pragma unroll
            for (int off = 1; off < 32; off <<= 1) {
                float n = __shfl_up_sync(0xffffffffu, c, off);
                if (lane >= off) c += n;
            }

            // t_lane = a^lane * (a * t_carry + prefix)
            const float tv = apow * fmaf(a, t, c);
            orow[r * 128 + j * 32 + lane] = tv;

            t = __shfl_sync(0xffffffffu, tv, 31);
        }

        // all lanes done reading this tile -> refill the slot with tile r+D
        __syncwarp();
        if (lane == 0 && r + D < NSUPER) {
            mbar_expect_tx(mb[slot], TILEB);
            bulk_g2s(tl[slot], rowg + (size_t)(r + D) * TILEB, TILEB, mb[slot]);
        }
    }
}

extern "C" void kernel_launch(void* const* d_in, const int* in_sizes, int n_in,
                              void* d_out, int out_size)
{
    (void)in_sizes; (void)n_in; (void)out_size;
    const float* in = (const float*)d_in[0];
    const float* rR = (const float*)d_in[1];
    const float* rC = (const float*)d_in[2];
    const float* rA = (const float*)d_in[3];
    const float* rG = (const float*)d_in[4];
    float* out = (float*)d_out;

    // one warp per row: 8192 warps, 4 warps (128 threads) per block
    dim3 grid(NROWS / 4);
    dim3 block(BLOCK);
    rc_scan_kernel<<<grid, block>>>(in, rR, rC, rA, rG, out);
}